// round 10
// baseline (speedup 1.0000x reference)
#include <cuda_runtime.h>
#include <math.h>

// Fixed shape: features [8, 4096, 256] f32, scores [8, 4096, 1] f32.
#define BB 8
#define NN 4096
#define DD 256
#define ROWS_PER_WARP 8
#define WARPS 8
#define ROWS_PER_BLOCK (ROWS_PER_WARP * WARPS)      // 64
#define NBLOCKS ((BB * NN) / ROWS_PER_BLOCK)        // 512
#define BLOCKS_PER_B (NN / ROWS_PER_BLOCK)          // 64

// Scratch (device globals; no allocation allowed).
__device__ float g_inv[BB * NN];            // 1 / max(||x_row||, eps)
__device__ float g_part[NBLOCKS][DD];       // per-block partials of sum_n f[b,n,:]
__device__ float g_sumv[BB][DD];            // S_b = sum_n f[b,n,:]
__device__ float g_sum2[BB];                // ||S_b||^2
__device__ float g_bce[NBLOCKS];            // per-block BCE partials
// Grid-sync state. Reset to 0 by the final block each launch (graph replays).
__device__ int g_c1, g_c2, g_c3, g_f1, g_f2;

__device__ __forceinline__ void grid_arrive_wait(int* cnt, int* flag) {
    __syncthreads();
    if (threadIdx.x == 0) {
        __threadfence();
        int old = atomicAdd(cnt, 1);
        if (old == NBLOCKS - 1) {
            atomicExch(flag, 1);
        } else {
            while (*(volatile int*)flag == 0) __nanosleep(64);
        }
        __threadfence();
    }
    __syncthreads();
}

__global__ void __launch_bounds__(256, 4)
k_all(const float* __restrict__ feat, const float* __restrict__ scores,
      float* __restrict__ out) {
    __shared__ float sp[WARPS][DD];                 // 8 KB, reused across phases
    const int w = threadIdx.x >> 5, lane = threadIdx.x & 31;
    const int r0 = blockIdx.x * ROWS_PER_BLOCK + w * ROWS_PER_WARP;
    const float4* fp = (const float4*)feat;

    // ---------------- Phase 1: row norms + per-block partial sums -----------
    {
        float a0 = 0.f, a1 = 0.f, a2 = 0.f, a3 = 0.f;
        float a4 = 0.f, a5 = 0.f, a6 = 0.f, a7 = 0.f;
        float myinv = 0.f;
#pragma unroll
        for (int j = 0; j < ROWS_PER_WARP; j++) {
            const int r = r0 + j;
            float4 a = fp[r * 64 + lane];
            float4 c = fp[r * 64 + 32 + lane];
            float ss = a.x * a.x + a.y * a.y + a.z * a.z + a.w * a.w
                     + c.x * c.x + c.y * c.y + c.z * c.z + c.w * c.w;
#pragma unroll
            for (int o = 16; o > 0; o >>= 1)
                ss += __shfl_xor_sync(0xffffffffu, ss, o);
            float inv = 1.0f / fmaxf(sqrtf(ss), 1e-12f);   // F.normalize eps
            if (lane == j) myinv = inv;
            a0 += a.x * inv; a1 += a.y * inv; a2 += a.z * inv; a3 += a.w * inv;
            a4 += c.x * inv; a5 += c.y * inv; a6 += c.z * inv; a7 += c.w * inv;
        }
        if (lane < ROWS_PER_WARP) g_inv[r0 + lane] = myinv;

        sp[w][lane * 4 + 0] = a0; sp[w][lane * 4 + 1] = a1;
        sp[w][lane * 4 + 2] = a2; sp[w][lane * 4 + 3] = a3;
        sp[w][128 + lane * 4 + 0] = a4; sp[w][128 + lane * 4 + 1] = a5;
        sp[w][128 + lane * 4 + 2] = a6; sp[w][128 + lane * 4 + 3] = a7;
        __syncthreads();

        const int d = threadIdx.x;
        float s = sp[0][d];
#pragma unroll
        for (int i = 1; i < WARPS; i++) s += sp[i][d];
        g_part[blockIdx.x][d] = s;
    }

    grid_arrive_wait(&g_c1, &g_f1);

    // ---------------- Phase 2: blocks 0..7 reduce partials into S_b ---------
    if (blockIdx.x < BB) {
        const int b = blockIdx.x, d = threadIdx.x;
        float s = 0.f;
#pragma unroll 8
        for (int i = 0; i < BLOCKS_PER_B; i++) s += g_part[b * BLOCKS_PER_B + i][d];
        g_sumv[b][d] = s;

        __syncthreads();                    // sp reuse barrier
        sp[0][d] = s * s;
        __syncthreads();
        for (int st = 128; st > 0; st >>= 1) {
            if (d < st) sp[0][d] += sp[0][d + st];
            __syncthreads();
        }
        if (d == 0) g_sum2[b] = sp[0][0];
    }

    grid_arrive_wait(&g_c2, &g_f2);

    // ---------------- Phase 3: dots vs S_b + BCE terms ----------------------
    {
        const int b = blockIdx.x / BLOCKS_PER_B;
        float4* sv = (float4*)sp[0];                // 256 floats = 64 float4
        if (threadIdx.x < 64) sv[threadIdx.x] = ((const float4*)g_sumv[b])[threadIdx.x];
        __syncthreads();

        const float4 sA = sv[lane];
        const float4 sB = sv[32 + lane];

        float mydot = 0.f;
#pragma unroll
        for (int j = 0; j < ROWS_PER_WARP; j++) {
            const int r = r0 + j;
            float4 a = fp[r * 64 + lane];
            float4 c = fp[r * 64 + 32 + lane];
            float dt = a.x * sA.x + a.y * sA.y + a.z * sA.z + a.w * sA.w
                     + c.x * sB.x + c.y * sB.y + c.z * sB.z + c.w * sB.w;
#pragma unroll
            for (int o = 16; o > 0; o >>= 1)
                dt += __shfl_xor_sync(0xffffffffu, dt, o);
            if (lane == j) mydot = dt;
        }

        float term = 0.f;
        if (lane < ROWS_PER_WARP) {
            const int r = r0 + lane;
            const float inv = g_inv[r];
            const float sim = (mydot * inv - 1.0f) * (1.0f / (float)(NN - 1));
            const float t = 1.0f - fmaxf(sim, 0.0f);
            const float sc = scores[r];
            const float ls = fmaxf(logf(sc), -100.0f);   // torch BCELoss clamp
            const float l1 = fmaxf(log1pf(-sc), -100.0f);
            term = t * ls + (1.0f - t) * l1;
        }
#pragma unroll
        for (int o = 16; o > 0; o >>= 1)
            term += __shfl_xor_sync(0xffffffffu, term, o);
        __syncthreads();                              // sv no longer needed
        if (lane == 0) sp[1][w] = term;
        __syncthreads();
        if (threadIdx.x == 0) {
            float s = 0.f;
#pragma unroll
            for (int i = 0; i < WARPS; i++) s += sp[1][i];
            g_bce[blockIdx.x] = s;
        }
    }

    // ---------------- Final: last-arriving block reduces + resets -----------
    __shared__ int islast;
    __syncthreads();
    if (threadIdx.x == 0) {
        __threadfence();
        islast = (atomicAdd(&g_c3, 1) == NBLOCKS - 1) ? 1 : 0;
    }
    __syncthreads();
    if (islast) {
        __threadfence();
        const int t = threadIdx.x;
        // 256 threads over 512 partials: fixed-order pairwise, then tree.
        float v = g_bce[t] + g_bce[t + 256];
        sp[0][t] = v;
        __syncthreads();
        for (int st = 128; st > 0; st >>= 1) {
            if (t < st) sp[0][t] += sp[0][t + st];
            __syncthreads();
        }
        if (t == 0) {
            float s2 = 0.f;
#pragma unroll
            for (int b = 0; b < BB; b++) s2 += g_sum2[b];
            const float bce = -sp[0][0] / (float)(BB * NN);
            const float feat_loss = 1.0f - s2 / ((float)BB * (float)NN * (float)NN);
            out[0] = bce + feat_loss;
            // Reset sync state for next graph replay.
            g_c1 = 0; g_c2 = 0; g_c3 = 0; g_f1 = 0; g_f2 = 0;
            __threadfence();
        }
    }
}

extern "C" void kernel_launch(void* const* d_in, const int* in_sizes, int n_in,
                              void* d_out, int out_size) {
    const float* feat = (const float*)d_in[0];    // [8, 4096, 256] f32
    const float* scores = (const float*)d_in[1];  // [8, 4096, 1]  f32
    float* out = (float*)d_out;                   // scalar f32
    k_all<<<NBLOCKS, 256>>>(feat, scores, out);
}